// round 14
// baseline (speedup 1.0000x reference)
#include <cuda_runtime.h>
#include <math.h>

#define B_   4
#define H_   16
#define S_   4096
#define D_   64
#define BH_  64
#define SC1  16          // pass1 split-K chunks
#define CH1  256         // rows per pass1 chunk

// ---- device scratch (no allocations allowed) ----
__device__ float4 g_tab4[S_ * 8];                  // (cos0,sin0,cos1,sin1) per (s, pair-group)
__device__ float  g_partA[BH_ * SC1 * D_ * D_];    // split-K partials
__device__ float  g_partK[BH_ * SC1 * D_];
__device__ float  g_A[BH_ * D_ * D_];              // reduced A[d][e]
__device__ float  g_ksum[BH_ * D_];

// Packed fp32x2 FMA — the only route to full fp32 rate on sm_103a (FFMA2).
__device__ __forceinline__ float2 ffma2(float2 a, float2 b, float2 c) {
    float2 d;
    asm("fma.rn.f32x2 %0, %1, %2, %3;"
        : "=l"(*reinterpret_cast<unsigned long long*>(&d))
        : "l"(*reinterpret_cast<unsigned long long*>(&a)),
          "l"(*reinterpret_cast<unsigned long long*>(&b)),
          "l"(*reinterpret_cast<unsigned long long*>(&c)));
    return d;
}

__device__ __forceinline__ float elu1(float x) {
    return x > 0.0f ? x + 1.0f : expm1f(x) + 1.0f;
}

// ---- RoPE table: theta in f64 like the reference, precise f32 cos/sin ----
__global__ void k_tab() {
    int idx = blockIdx.x * blockDim.x + threadIdx.x;
    if (idx >= S_ * 8) return;
    int t = idx >> 3, j = idx & 7;
    double td = (double)t;
    double inv0 = pow(10000.0, -(double)(2 * j) / 16.0);
    double inv1 = pow(10000.0, -(double)(2 * j + 1) / 16.0);
    float th0 = (float)(td * inv0);
    float th1 = (float)(td * inv1);
    g_tab4[idx] = make_float4(cosf(th0), sinf(th0), cosf(th1), sinf(th1));
}

// ---- Pass 1: A_partial = Kr^T V over 256-row S-chunk; ksum partials ----
// 128 threads / 4 warps. Warp w covers ALL 64 d-rows x 16 e-cols (e = 16w..).
// Lane owns d-pair (2l, 2l+1): K read as conflict-free LDS.64, V as warp-
// uniform broadcast float4s -> 0.31 smem-bytes/MAC, FMA-bound.
__global__ void __launch_bounds__(128) k_pass1(const float* __restrict__ K,
                                               const float* __restrict__ V,
                                               const int*   __restrict__ mask) {
    __shared__ __align__(16) float Ks[64 * 64];
    __shared__ __align__(16) float Vs[64 * 64];
    __shared__ __align__(16) float red[8 * 64];

    int tid = threadIdx.x;
    int sc = blockIdx.x, bh = blockIdx.y;
    int b = bh >> 4;
    int c4 = tid & 15, rq = tid >> 4;        // load-phase coords (8 row-groups)
    int lane = tid & 31, w = tid >> 5;       // compute-phase coords

    const float4* K4 = reinterpret_cast<const float4*>(K) + (size_t)bh * (S_ * 16);
    const float4* V4 = reinterpret_cast<const float4*>(V) + (size_t)bh * (S_ * 16);
    const int* mrow = mask + b * S_;

    float2 acc[16];
    #pragma unroll
    for (int e = 0; e < 16; e++) acc[e] = make_float2(0.f, 0.f);
    float4 ksacc = make_float4(0.f, 0.f, 0.f, 0.f);

    for (int tt = 0; tt < CH1 / 64; tt++) {
        int sbase = sc * CH1 + tt * 64;
        #pragma unroll
        for (int it = 0; it < 8; it++) {
            int rl = rq + 8 * it;
            int s = sbase + rl;
            float m = (float)mrow[s];
            float4 kv = K4[s * 16 + c4];
            float f0 = elu1(kv.x) * m;
            float f1 = elu1(kv.y) * m;
            float f2 = elu1(kv.z) * m;
            float f3 = elu1(kv.w) * m;
            ksacc.x += fabsf(f0); ksacc.y += fabsf(f1);
            ksacc.z += fabsf(f2); ksacc.w += fabsf(f3);
            if (c4 < 8) {  // rotary half (cols < 32)
                float4 t4 = g_tab4[s * 8 + c4];
                float r0 = f0 * t4.x - f1 * t4.y;
                float r1 = f1 * t4.x + f0 * t4.y;
                float r2 = f2 * t4.z - f3 * t4.w;
                float r3 = f3 * t4.z + f2 * t4.w;
                f0 = r0; f1 = r1; f2 = r2; f3 = r3;
            }
            reinterpret_cast<float4*>(Ks)[rl * 16 + c4] = make_float4(f0, f1, f2, f3);
            reinterpret_cast<float4*>(Vs)[rl * 16 + c4] = V4[s * 16 + c4];
        }
        __syncthreads();
        #pragma unroll 4
        for (int s = 0; s < 64; s++) {
            float2 k2 = *reinterpret_cast<const float2*>(&Ks[s * 64 + 2 * lane]);
            float4 v0 = reinterpret_cast<const float4*>(Vs)[s * 16 + w * 4];
            float4 v1 = reinterpret_cast<const float4*>(Vs)[s * 16 + w * 4 + 1];
            float4 v2 = reinterpret_cast<const float4*>(Vs)[s * 16 + w * 4 + 2];
            float4 v3 = reinterpret_cast<const float4*>(Vs)[s * 16 + w * 4 + 3];
            acc[0]  = ffma2(k2, make_float2(v0.x, v0.x), acc[0]);
            acc[1]  = ffma2(k2, make_float2(v0.y, v0.y), acc[1]);
            acc[2]  = ffma2(k2, make_float2(v0.z, v0.z), acc[2]);
            acc[3]  = ffma2(k2, make_float2(v0.w, v0.w), acc[3]);
            acc[4]  = ffma2(k2, make_float2(v1.x, v1.x), acc[4]);
            acc[5]  = ffma2(k2, make_float2(v1.y, v1.y), acc[5]);
            acc[6]  = ffma2(k2, make_float2(v1.z, v1.z), acc[6]);
            acc[7]  = ffma2(k2, make_float2(v1.w, v1.w), acc[7]);
            acc[8]  = ffma2(k2, make_float2(v2.x, v2.x), acc[8]);
            acc[9]  = ffma2(k2, make_float2(v2.y, v2.y), acc[9]);
            acc[10] = ffma2(k2, make_float2(v2.z, v2.z), acc[10]);
            acc[11] = ffma2(k2, make_float2(v2.w, v2.w), acc[11]);
            acc[12] = ffma2(k2, make_float2(v3.x, v3.x), acc[12]);
            acc[13] = ffma2(k2, make_float2(v3.y, v3.y), acc[13]);
            acc[14] = ffma2(k2, make_float2(v3.z, v3.z), acc[14]);
            acc[15] = ffma2(k2, make_float2(v3.w, v3.w), acc[15]);
        }
        __syncthreads();
    }

    // store partial A tile: lane holds rows (2l, 2l+1), cols w*16..w*16+15
    float4* pA4 = reinterpret_cast<float4*>(g_partA + (size_t)(bh * SC1 + sc) * 4096);
    int d0 = 2 * lane;
    #pragma unroll
    for (int i = 0; i < 4; i++) {
        pA4[d0 * 16 + w * 4 + i] =
            make_float4(acc[4 * i].x, acc[4 * i + 1].x, acc[4 * i + 2].x, acc[4 * i + 3].x);
        pA4[(d0 + 1) * 16 + w * 4 + i] =
            make_float4(acc[4 * i].y, acc[4 * i + 1].y, acc[4 * i + 2].y, acc[4 * i + 3].y);
    }
    // deterministic fixed-order ksum partial reduction
    reinterpret_cast<float4*>(red)[rq * 16 + c4] = ksacc;
    __syncthreads();
    if (tid < 64) {
        float ssum = 0.f;
        #pragma unroll
        for (int i = 0; i < 8; i++) ssum += red[i * 64 + tid];
        g_partK[(bh * SC1 + sc) * 64 + tid] = ssum;
    }
}

// ---- fixed-order split-K reduction ----
__global__ void __launch_bounds__(256) k_reduce() {
    int bh = blockIdx.x, tid = threadIdx.x;
    for (int idx = tid; idx < 4096; idx += 256) {
        float s = 0.f;
        #pragma unroll
        for (int p = 0; p < SC1; p++)
            s += g_partA[(size_t)(bh * SC1 + p) * 4096 + idx];
        g_A[bh * 4096 + idx] = s;
    }
    if (tid < 64) {
        float s = 0.f;
        #pragma unroll
        for (int p = 0; p < SC1; p++)
            s += g_partK[(bh * SC1 + p) * 64 + tid];
        g_ksum[bh * 64 + tid] = s;
    }
}

// ---- Pass 2: q-in-registers GEMV per row, broadcast A from smem ----
// Block = 64 rows x 64 cols, 256 threads. Thread = (row, col-quarter):
// quarter = tid&3, row = tid>>2. Warp = 8 rows x 4 quarters -> A loads have
// <=4 distinct addresses per instruction (broadcast, N=1); out stores coalesced.
__global__ void __launch_bounds__(256, 2) k_pass2(const float* __restrict__ Q,
                                                  float* __restrict__ out) {
    __shared__ __align__(16) float As[4096];
    __shared__ __align__(16) float ksm[64];
    int tid = threadIdx.x;
    int st = blockIdx.x, bh = blockIdx.y;

    for (int i = tid; i < 4096; i += 256) As[i] = g_A[bh * 4096 + i];
    if (tid < 64) ksm[tid] = g_ksum[bh * 64 + tid];
    __syncthreads();

    int q4 = tid & 3, row = tid >> 2;
    int s = st * 64 + row;
    const float4* Q4 = reinterpret_cast<const float4*>(Q) + ((size_t)bh * S_ + s) * 16;

    float q[64];
    float nrm = 0.f;
    #pragma unroll
    for (int j = 0; j < 16; j++) {
        float4 v = Q4[j];
        float f0 = elu1(v.x * 0.125f);
        float f1 = elu1(v.y * 0.125f);
        float f2 = elu1(v.z * 0.125f);
        float f3 = elu1(v.w * 0.125f);
        float4 kv = reinterpret_cast<const float4*>(ksm)[j];   // warp-uniform
        nrm += f0 * kv.x + f1 * kv.y + f2 * kv.z + f3 * kv.w;  // pre-RoPE Qf
        q[4 * j] = f0; q[4 * j + 1] = f1; q[4 * j + 2] = f2; q[4 * j + 3] = f3;
    }
    #pragma unroll
    for (int j = 0; j < 8; j++) {   // rotary half: cols 0..31
        float4 t4 = g_tab4[s * 8 + j];
        float a = q[4 * j], b2 = q[4 * j + 1];
        q[4 * j]     = a * t4.x - b2 * t4.y;
        q[4 * j + 1] = b2 * t4.x + a * t4.y;
        a = q[4 * j + 2]; b2 = q[4 * j + 3];
        q[4 * j + 2] = a * t4.z - b2 * t4.w;
        q[4 * j + 3] = b2 * t4.z + a * t4.w;
    }
    float rinv = 1.0f / nrm;

    float2 acc[8];
    #pragma unroll
    for (int c = 0; c < 8; c++) acc[c] = make_float2(0.f, 0.f);

    const float4* Ab = reinterpret_cast<const float4*>(As) + q4 * 4;
    #pragma unroll
    for (int k = 0; k < 64; k++) {
        float2 qk = make_float2(q[k], q[k]);
        float4 a0 = Ab[k * 16];
        float4 a1 = Ab[k * 16 + 1];
        float4 a2 = Ab[k * 16 + 2];
        float4 a3 = Ab[k * 16 + 3];
        acc[0] = ffma2(qk, make_float2(a0.x, a0.y), acc[0]);
        acc[1] = ffma2(qk, make_float2(a0.z, a0.w), acc[1]);
        acc[2] = ffma2(qk, make_float2(a1.x, a1.y), acc[2]);
        acc[3] = ffma2(qk, make_float2(a1.z, a1.w), acc[3]);
        acc[4] = ffma2(qk, make_float2(a2.x, a2.y), acc[4]);
        acc[5] = ffma2(qk, make_float2(a2.z, a2.w), acc[5]);
        acc[6] = ffma2(qk, make_float2(a3.x, a3.y), acc[6]);
        acc[7] = ffma2(qk, make_float2(a3.z, a3.w), acc[7]);
    }

    float4* outp = reinterpret_cast<float4*>(out) + ((size_t)bh * S_ + s) * 16 + q4 * 4;
    #pragma unroll
    for (int i = 0; i < 4; i++) {
        outp[i] = make_float4(acc[2 * i].x * rinv, acc[2 * i].y * rinv,
                              acc[2 * i + 1].x * rinv, acc[2 * i + 1].y * rinv);
    }
}

extern "C" void kernel_launch(void* const* d_in, const int* in_sizes, int n_in,
                              void* d_out, int out_size) {
    const float* Q   = (const float*)d_in[0];
    const float* K   = (const float*)d_in[1];
    const float* V   = (const float*)d_in[2];
    const int* mask  = (const int*)d_in[3];
    float* out = (float*)d_out;

    k_tab<<<(S_ * 8 + 255) / 256, 256>>>();
    k_pass1<<<dim3(SC1, BH_), 128>>>(K, V, mask);
    k_reduce<<<BH_, 256>>>();
    k_pass2<<<dim3(S_ / 64, BH_), 256>>>(Q, out);
}

// round 15
// speedup vs baseline: 1.0056x; 1.0056x over previous
#include <cuda_runtime.h>
#include <math.h>

#define B_   4
#define H_   16
#define S_   4096
#define D_   64
#define BH_  64
#define SC1  16          // pass1 split-K chunks
#define CH1  256         // rows per pass1 chunk

// ---- device scratch (no allocations allowed) ----
__device__ float4 g_tab4[S_ * 8];                  // (cos0,sin0,cos1,sin1) per (s, pair-group)
__device__ float  g_partA[BH_ * SC1 * D_ * D_];    // split-K partials
__device__ float  g_partK[BH_ * SC1 * D_];
__device__ float  g_A[BH_ * D_ * D_];              // reduced A[d][e]
__device__ float  g_ksum[BH_ * D_];

// Packed fp32x2 FMA — the only route to full fp32 rate on sm_103a (FFMA2).
__device__ __forceinline__ float2 ffma2(float2 a, float2 b, float2 c) {
    float2 d;
    asm("fma.rn.f32x2 %0, %1, %2, %3;"
        : "=l"(*reinterpret_cast<unsigned long long*>(&d))
        : "l"(*reinterpret_cast<unsigned long long*>(&a)),
          "l"(*reinterpret_cast<unsigned long long*>(&b)),
          "l"(*reinterpret_cast<unsigned long long*>(&c)));
    return d;
}

__device__ __forceinline__ float elu1(float x) {
    return x > 0.0f ? x + 1.0f : expm1f(x) + 1.0f;
}

// ---- RoPE table: theta in f64 like the reference, precise f32 cos/sin ----
__global__ void k_tab() {
    int idx = blockIdx.x * blockDim.x + threadIdx.x;
    if (idx >= S_ * 8) return;
    int t = idx >> 3, j = idx & 7;
    double td = (double)t;
    double inv0 = pow(10000.0, -(double)(2 * j) / 16.0);
    double inv1 = pow(10000.0, -(double)(2 * j + 1) / 16.0);
    float th0 = (float)(td * inv0);
    float th1 = (float)(td * inv1);
    g_tab4[idx] = make_float4(cosf(th0), sinf(th0), cosf(th1), sinf(th1));
}

// ---- Pass 1: A_partial = Kr^T V over 256-row S-chunk; ksum partials ----
// 128 threads / 4 warps. Warp w covers ALL 64 d-rows x 16 e-cols (e = 16w..).
// Lane owns d-pair (2l, 2l+1): K read as conflict-free LDS.64, V as warp-
// uniform broadcast float4s -> 0.31 smem-bytes/MAC, FMA-bound.
__global__ void __launch_bounds__(128) k_pass1(const float* __restrict__ K,
                                               const float* __restrict__ V,
                                               const int*   __restrict__ mask) {
    __shared__ __align__(16) float Ks[64 * 64];
    __shared__ __align__(16) float Vs[64 * 64];
    __shared__ __align__(16) float red[8 * 64];

    int tid = threadIdx.x;
    int sc = blockIdx.x, bh = blockIdx.y;
    int b = bh >> 4;
    int c4 = tid & 15, rq = tid >> 4;        // load-phase coords (8 row-groups)
    int lane = tid & 31, w = tid >> 5;       // compute-phase coords

    const float4* K4 = reinterpret_cast<const float4*>(K) + (size_t)bh * (S_ * 16);
    const float4* V4 = reinterpret_cast<const float4*>(V) + (size_t)bh * (S_ * 16);
    const int* mrow = mask + b * S_;

    float2 acc[16];
    #pragma unroll
    for (int e = 0; e < 16; e++) acc[e] = make_float2(0.f, 0.f);
    float4 ksacc = make_float4(0.f, 0.f, 0.f, 0.f);

    for (int tt = 0; tt < CH1 / 64; tt++) {
        int sbase = sc * CH1 + tt * 64;
        #pragma unroll
        for (int it = 0; it < 8; it++) {
            int rl = rq + 8 * it;
            int s = sbase + rl;
            float m = (float)mrow[s];
            float4 kv = K4[s * 16 + c4];
            float f0 = elu1(kv.x) * m;
            float f1 = elu1(kv.y) * m;
            float f2 = elu1(kv.z) * m;
            float f3 = elu1(kv.w) * m;
            ksacc.x += fabsf(f0); ksacc.y += fabsf(f1);
            ksacc.z += fabsf(f2); ksacc.w += fabsf(f3);
            if (c4 < 8) {  // rotary half (cols < 32)
                float4 t4 = g_tab4[s * 8 + c4];
                float r0 = f0 * t4.x - f1 * t4.y;
                float r1 = f1 * t4.x + f0 * t4.y;
                float r2 = f2 * t4.z - f3 * t4.w;
                float r3 = f3 * t4.z + f2 * t4.w;
                f0 = r0; f1 = r1; f2 = r2; f3 = r3;
            }
            reinterpret_cast<float4*>(Ks)[rl * 16 + c4] = make_float4(f0, f1, f2, f3);
            reinterpret_cast<float4*>(Vs)[rl * 16 + c4] = V4[s * 16 + c4];
        }
        __syncthreads();
        #pragma unroll 4
        for (int s = 0; s < 64; s++) {
            float2 k2 = *reinterpret_cast<const float2*>(&Ks[s * 64 + 2 * lane]);
            float4 v0 = reinterpret_cast<const float4*>(Vs)[s * 16 + w * 4];
            float4 v1 = reinterpret_cast<const float4*>(Vs)[s * 16 + w * 4 + 1];
            float4 v2 = reinterpret_cast<const float4*>(Vs)[s * 16 + w * 4 + 2];
            float4 v3 = reinterpret_cast<const float4*>(Vs)[s * 16 + w * 4 + 3];
            acc[0]  = ffma2(k2, make_float2(v0.x, v0.x), acc[0]);
            acc[1]  = ffma2(k2, make_float2(v0.y, v0.y), acc[1]);
            acc[2]  = ffma2(k2, make_float2(v0.z, v0.z), acc[2]);
            acc[3]  = ffma2(k2, make_float2(v0.w, v0.w), acc[3]);
            acc[4]  = ffma2(k2, make_float2(v1.x, v1.x), acc[4]);
            acc[5]  = ffma2(k2, make_float2(v1.y, v1.y), acc[5]);
            acc[6]  = ffma2(k2, make_float2(v1.z, v1.z), acc[6]);
            acc[7]  = ffma2(k2, make_float2(v1.w, v1.w), acc[7]);
            acc[8]  = ffma2(k2, make_float2(v2.x, v2.x), acc[8]);
            acc[9]  = ffma2(k2, make_float2(v2.y, v2.y), acc[9]);
            acc[10] = ffma2(k2, make_float2(v2.z, v2.z), acc[10]);
            acc[11] = ffma2(k2, make_float2(v2.w, v2.w), acc[11]);
            acc[12] = ffma2(k2, make_float2(v3.x, v3.x), acc[12]);
            acc[13] = ffma2(k2, make_float2(v3.y, v3.y), acc[13]);
            acc[14] = ffma2(k2, make_float2(v3.z, v3.z), acc[14]);
            acc[15] = ffma2(k2, make_float2(v3.w, v3.w), acc[15]);
        }
        __syncthreads();
    }

    // store partial A tile: lane holds rows (2l, 2l+1), cols w*16..w*16+15
    float4* pA4 = reinterpret_cast<float4*>(g_partA + (size_t)(bh * SC1 + sc) * 4096);
    int d0 = 2 * lane;
    #pragma unroll
    for (int i = 0; i < 4; i++) {
        pA4[d0 * 16 + w * 4 + i] =
            make_float4(acc[4 * i].x, acc[4 * i + 1].x, acc[4 * i + 2].x, acc[4 * i + 3].x);
        pA4[(d0 + 1) * 16 + w * 4 + i] =
            make_float4(acc[4 * i].y, acc[4 * i + 1].y, acc[4 * i + 2].y, acc[4 * i + 3].y);
    }
    // deterministic fixed-order ksum partial reduction
    reinterpret_cast<float4*>(red)[rq * 16 + c4] = ksacc;
    __syncthreads();
    if (tid < 64) {
        float ssum = 0.f;
        #pragma unroll
        for (int i = 0; i < 8; i++) ssum += red[i * 64 + tid];
        g_partK[(bh * SC1 + sc) * 64 + tid] = ssum;
    }
}

// ---- fixed-order split-K reduction ----
__global__ void __launch_bounds__(256) k_reduce() {
    int bh = blockIdx.x, tid = threadIdx.x;
    for (int idx = tid; idx < 4096; idx += 256) {
        float s = 0.f;
        #pragma unroll
        for (int p = 0; p < SC1; p++)
            s += g_partA[(size_t)(bh * SC1 + p) * 4096 + idx];
        g_A[bh * 4096 + idx] = s;
    }
    if (tid < 64) {
        float s = 0.f;
        #pragma unroll
        for (int p = 0; p < SC1; p++)
            s += g_partK[(bh * SC1 + p) * 64 + tid];
        g_ksum[bh * 64 + tid] = s;
    }
}

// ---- Pass 2: q-in-registers GEMV per row, broadcast A from smem ----
// Block = 64 rows x 64 cols, 256 threads. Thread = (row, col-quarter):
// quarter = tid&3, row = tid>>2. Warp = 8 rows x 4 quarters -> A loads have
// <=4 distinct addresses per instruction (broadcast, N=1); out stores coalesced.
__global__ void __launch_bounds__(256, 2) k_pass2(const float* __restrict__ Q,
                                                  float* __restrict__ out) {
    __shared__ __align__(16) float As[4096];
    __shared__ __align__(16) float ksm[64];
    int tid = threadIdx.x;
    int st = blockIdx.x, bh = blockIdx.y;

    for (int i = tid; i < 4096; i += 256) As[i] = g_A[bh * 4096 + i];
    if (tid < 64) ksm[tid] = g_ksum[bh * 64 + tid];
    __syncthreads();

    int q4 = tid & 3, row = tid >> 2;
    int s = st * 64 + row;
    const float4* Q4 = reinterpret_cast<const float4*>(Q) + ((size_t)bh * S_ + s) * 16;

    float q[64];
    float nrm = 0.f;
    #pragma unroll
    for (int j = 0; j < 16; j++) {
        float4 v = Q4[j];
        float f0 = elu1(v.x * 0.125f);
        float f1 = elu1(v.y * 0.125f);
        float f2 = elu1(v.z * 0.125f);
        float f3 = elu1(v.w * 0.125f);
        float4 kv = reinterpret_cast<const float4*>(ksm)[j];   // warp-uniform
        nrm += f0 * kv.x + f1 * kv.y + f2 * kv.z + f3 * kv.w;  // pre-RoPE Qf
        q[4 * j] = f0; q[4 * j + 1] = f1; q[4 * j + 2] = f2; q[4 * j + 3] = f3;
    }
    #pragma unroll
    for (int j = 0; j < 8; j++) {   // rotary half: cols 0..31
        float4 t4 = g_tab4[s * 8 + j];
        float a = q[4 * j], b2 = q[4 * j + 1];
        q[4 * j]     = a * t4.x - b2 * t4.y;
        q[4 * j + 1] = b2 * t4.x + a * t4.y;
        a = q[4 * j + 2]; b2 = q[4 * j + 3];
        q[4 * j + 2] = a * t4.z - b2 * t4.w;
        q[4 * j + 3] = b2 * t4.z + a * t4.w;
    }
    float rinv = 1.0f / nrm;

    float2 acc[8];
    #pragma unroll
    for (int c = 0; c < 8; c++) acc[c] = make_float2(0.f, 0.f);

    const float4* Ab = reinterpret_cast<const float4*>(As) + q4 * 4;
    #pragma unroll
    for (int k = 0; k < 64; k++) {
        float2 qk = make_float2(q[k], q[k]);
        float4 a0 = Ab[k * 16];
        float4 a1 = Ab[k * 16 + 1];
        float4 a2 = Ab[k * 16 + 2];
        float4 a3 = Ab[k * 16 + 3];
        acc[0] = ffma2(qk, make_float2(a0.x, a0.y), acc[0]);
        acc[1] = ffma2(qk, make_float2(a0.z, a0.w), acc[1]);
        acc[2] = ffma2(qk, make_float2(a1.x, a1.y), acc[2]);
        acc[3] = ffma2(qk, make_float2(a1.z, a1.w), acc[3]);
        acc[4] = ffma2(qk, make_float2(a2.x, a2.y), acc[4]);
        acc[5] = ffma2(qk, make_float2(a2.z, a2.w), acc[5]);
        acc[6] = ffma2(qk, make_float2(a3.x, a3.y), acc[6]);
        acc[7] = ffma2(qk, make_float2(a3.z, a3.w), acc[7]);
    }

    float4* outp = reinterpret_cast<float4*>(out) + ((size_t)bh * S_ + s) * 16 + q4 * 4;
    #pragma unroll
    for (int i = 0; i < 4; i++) {
        outp[i] = make_float4(acc[2 * i].x * rinv, acc[2 * i].y * rinv,
                              acc[2 * i + 1].x * rinv, acc[2 * i + 1].y * rinv);
    }
}

extern "C" void kernel_launch(void* const* d_in, const int* in_sizes, int n_in,
                              void* d_out, int out_size) {
    const float* Q   = (const float*)d_in[0];
    const float* K   = (const float*)d_in[1];
    const float* V   = (const float*)d_in[2];
    const int* mask  = (const int*)d_in[3];
    float* out = (float*)d_out;

    k_tab<<<(S_ * 8 + 255) / 256, 256>>>();
    k_pass1<<<dim3(SC1, BH_), 128>>>(K, V, mask);
    k_reduce<<<BH_, 256>>>();
    k_pass2<<<dim3(S_ / 64, BH_), 256>>>(Q, out);
}